// round 5
// baseline (speedup 1.0000x reference)
#include <cuda_runtime.h>
#include <cuda_bf16.h>
#include <math.h>

// Problem dims (fixed by the dataset)
#define SS 128      // sequence length
#define BB 64       // batch
#define HH 1024     // hidden = embedding dim
#define VV 10000    // vocab
#define MM (SS*BB)  // 8192 rows for the batched GEMMs
#define BH (BB*HH)  // 65536
#define GRIDN 128   // recurrence grid (128 j-tiles of 8)

// ---------------- device scratch (no allocations allowed) ----------------
__device__ __align__(16) float g_pre0[MM * HH];   // emb@W_ih0^T + b_ih0 (all steps)
__device__ __align__(16) float g_pre1[MM * HH];   // H0all@W_ih1^T + b_ih1 + b_hh1
__device__ __align__(16) float g_H0[MM * HH];     // layer-0 hidden for every step
__device__ __align__(16) float g_H1[MM * HH];     // layer-1 hidden for every step (= X)
__device__ __align__(16) float g_bias1c[HH];      // b_ih1 + b_hh1
__device__ unsigned g_arrive;                     // grid barrier: arrival counter
__device__ unsigned g_release;                    // grid barrier: released generation

// ---------------- helpers ----------------
__device__ __forceinline__ unsigned ldcg_u(const unsigned* p) {
    unsigned v; asm volatile("ld.global.cg.u32 %0, [%1];" : "=r"(v) : "l"(p)); return v;
}
__device__ __forceinline__ unsigned smem_u32(const void* p) {
    unsigned a;
    asm("{ .reg .u64 t; cvta.to.shared.u64 t, %1; cvt.u32.u64 %0, t; }" : "=r"(a) : "l"(p));
    return a;
}
__device__ __forceinline__ void cp_async16(unsigned dst, const void* src) {
    asm volatile("cp.async.cg.shared.global [%0], [%1], 16;" :: "r"(dst), "l"(src));
}
__device__ __forceinline__ void cp_commit() {
    asm volatile("cp.async.commit_group;");
}
template<int N>
__device__ __forceinline__ void cp_wait() {
    asm volatile("cp.async.wait_group %0;" :: "n"(N));
}

// ---------------- grid-wide barrier (all GRIDN blocks resident) ----------
__device__ __forceinline__ void grid_barrier(unsigned want) {
    __syncthreads();
    if (threadIdx.x == 0) {
        __threadfence();
        unsigned prev = atomicAdd(&g_arrive, 1u);
        if (prev == want * GRIDN - 1u) {
            atomicExch(&g_release, want);
        }
        while (ldcg_u(&g_release) < want) { __nanosleep(32); }
    }
    __syncthreads();
}

// ---------------- generic tiled fp32 GEMM: C = A @ B^T + bias ----------------
template<bool GATHER>
__global__ void __launch_bounds__(256) sgemm_tn(
    const float* __restrict__ A,
    const float* __restrict__ emb,
    const int*   __restrict__ gidx,
    float scaleA,
    const float* __restrict__ Bm,
    const float* __restrict__ bias,
    float* __restrict__ C, int ldc,
    int N, int K)
{
    __shared__ float As[16][128 + 4];
    __shared__ float Bs[16][128 + 4];

    const int bm = blockIdx.y * 128;
    const int bn = blockIdx.x * 128;
    const int tid = threadIdx.x;
    const int tx = tid & 15;
    const int ty = tid >> 4;
    const int lr0 = tid >> 2;
    const int lr1 = lr0 + 64;
    const int lc4 = (tid & 3) * 4;

    const float* arow0;
    const float* arow1;
    if (GATHER) {
        arow0 = emb + (size_t)gidx[bm + lr0] * K;
        arow1 = emb + (size_t)gidx[bm + lr1] * K;
    } else {
        arow0 = A + (size_t)(bm + lr0) * K;
        arow1 = A + (size_t)(bm + lr1) * K;
    }
    const int  bn0 = bn + lr0, bn1 = bn + lr1;
    const bool v0 = bn0 < N, v1 = bn1 < N;
    const float* brow0 = Bm + (size_t)bn0 * K;
    const float* brow1 = Bm + (size_t)bn1 * K;

    float acc[8][8] = {};

    for (int k0 = 0; k0 < K; k0 += 16) {
        float4 a0 = *(const float4*)(arow0 + k0 + lc4);
        float4 a1 = *(const float4*)(arow1 + k0 + lc4);
        if (GATHER) {
            a0.x *= scaleA; a0.y *= scaleA; a0.z *= scaleA; a0.w *= scaleA;
            a1.x *= scaleA; a1.y *= scaleA; a1.z *= scaleA; a1.w *= scaleA;
        }
        float4 b0 = v0 ? *(const float4*)(brow0 + k0 + lc4) : make_float4(0.f,0.f,0.f,0.f);
        float4 b1 = v1 ? *(const float4*)(brow1 + k0 + lc4) : make_float4(0.f,0.f,0.f,0.f);

        As[lc4+0][lr0] = a0.x; As[lc4+1][lr0] = a0.y; As[lc4+2][lr0] = a0.z; As[lc4+3][lr0] = a0.w;
        As[lc4+0][lr1] = a1.x; As[lc4+1][lr1] = a1.y; As[lc4+2][lr1] = a1.z; As[lc4+3][lr1] = a1.w;
        Bs[lc4+0][lr0] = b0.x; Bs[lc4+1][lr0] = b0.y; Bs[lc4+2][lr0] = b0.z; Bs[lc4+3][lr0] = b0.w;
        Bs[lc4+0][lr1] = b1.x; Bs[lc4+1][lr1] = b1.y; Bs[lc4+2][lr1] = b1.z; Bs[lc4+3][lr1] = b1.w;
        __syncthreads();

        #pragma unroll
        for (int kk = 0; kk < 16; kk++) {
            float4 av0 = *(const float4*)&As[kk][ty*8];
            float4 av1 = *(const float4*)&As[kk][ty*8 + 4];
            float4 bw0 = *(const float4*)&Bs[kk][tx*8];
            float4 bw1 = *(const float4*)&Bs[kk][tx*8 + 4];
            float a[8] = {av0.x, av0.y, av0.z, av0.w, av1.x, av1.y, av1.z, av1.w};
            float b[8] = {bw0.x, bw0.y, bw0.z, bw0.w, bw1.x, bw1.y, bw1.z, bw1.w};
            #pragma unroll
            for (int i = 0; i < 8; i++)
                #pragma unroll
                for (int j = 0; j < 8; j++)
                    acc[i][j] = fmaf(a[i], b[j], acc[i][j]);
        }
        __syncthreads();
    }

    #pragma unroll
    for (int i = 0; i < 8; i++) {
        const int m = bm + ty*8 + i;
        #pragma unroll
        for (int j = 0; j < 8; j++) {
            const int n = bn + tx*8 + j;
            if (n < N) C[(size_t)m * ldc + n] = acc[i][j] + bias[n];
        }
    }
}

// ---------------- single-layer recurrence scan (reduction-free) ----------------
// h(t) = tanh( pre[t] + h(t-1) @ W^T + bias )  for t = 0..SS-1
// 128 blocks x 512 threads. Block owns j-slice of 8 (W tile 8x1024 SMEM-resident).
// Each thread owns ONE output (b, j): full-K dot product. h(t-1) is streamed
// through double-buffered cp.async chunks of 256 k. One grid barrier per step.
#define W_LD2 1028                 // k-stride of W rows in SMEM (1028 % 32 == 4)
#define H_LD2 260                  // k-stride of h rows in SMEM  (260 % 32 == 4)
#define CHUNK 256
#define NCHUNK (HH / CHUNK)        // 4
#define REC_SMEM_FLOATS (8*W_LD2 + 2*64*H_LD2 + 16)

__global__ void __launch_bounds__(512, 1) rec_layer(
    const float* __restrict__ h_init,   // [64][1024] initial hidden for this layer
    const float* __restrict__ pre,      // [SS][64][1024] precomputed input drive
    const float* __restrict__ W,        // [1024][1024] recurrent weights (row = out j)
    const float* __restrict__ bias,     // [1024] or nullptr
    float* __restrict__ hslab)          // [SS][64][1024] output hidden per step
{
    extern __shared__ float sm[];
    float* Wsm = sm;                    // [8][W_LD2]
    float* Hs  = sm + 8 * W_LD2;        // [2][64][H_LD2]

    const int tid = threadIdx.x;
    const int j   = tid & 7;            // output column within tile
    const int b   = tid >> 3;           // batch row
    const int j0g = blockIdx.x * 8;

    // ---- one-time: W tile into SMEM (8 rows x 1024, padded stride)
    for (int idx = tid; idx < 2048; idx += 512) {
        const int jr = idx >> 8, f4 = idx & 255;
        *(float4*)&Wsm[jr * W_LD2 + f4 * 4] =
            *(const float4*)&W[(size_t)(j0g + jr) * HH + f4 * 4];
    }
    const float bj = bias ? bias[j0g + j] : 0.0f;
    __syncthreads();

    const unsigned hs_base = smem_u32(Hs);
    const float* wrow = &Wsm[j * W_LD2];

    unsigned barnum = 0;

    for (int t = 0; t < SS; t++) {
        const float* hsrc = t ? (hslab + (size_t)(t - 1) * BH) : h_init;

        // prefetch this thread's drive term early
        const float prev = __ldg(&pre[(size_t)t * BH + (size_t)b * HH + j0g + j]);

        // stage chunk 0
        {
            #pragma unroll
            for (int r = 0; r < 8; r++) {
                const int idx = tid + r * 512;            // 0..4095
                const int bb = idx >> 6, f4 = idx & 63;
                cp_async16(hs_base + (unsigned)((bb * H_LD2 + f4 * 4) * 4),
                           hsrc + (size_t)bb * HH + f4 * 4);
            }
            cp_commit();
        }

        float a0 = 0.f, a1 = 0.f, a2 = 0.f, a3 = 0.f;

        #pragma unroll
        for (int c = 0; c < NCHUNK; c++) {
            if (c + 1 < NCHUNK) {   // stage next chunk into other buffer
                const unsigned buf = (unsigned)((c + 1) & 1) * 64 * H_LD2 * 4;
                #pragma unroll
                for (int r = 0; r < 8; r++) {
                    const int idx = tid + r * 512;
                    const int bb = idx >> 6, f4 = idx & 63;
                    cp_async16(hs_base + buf + (unsigned)((bb * H_LD2 + f4 * 4) * 4),
                               hsrc + (size_t)bb * HH + (c + 1) * CHUNK + f4 * 4);
                }
                cp_commit();
                cp_wait<1>();
            } else {
                cp_wait<0>();
            }
            __syncthreads();

            const float* hb = &Hs[(c & 1) * 64 * H_LD2 + b * H_LD2];
            const float* wc = wrow + c * CHUNK;
            #pragma unroll 8
            for (int k = 0; k < CHUNK; k += 4) {
                const float4 h4 = *(const float4*)&hb[k];
                const float4 w4 = *(const float4*)&wc[k];
                a0 = fmaf(h4.x, w4.x, a0);
                a1 = fmaf(h4.y, w4.y, a1);
                a2 = fmaf(h4.z, w4.z, a2);
                a3 = fmaf(h4.w, w4.w, a3);
            }
            __syncthreads();
        }

        const float v = tanhf((a0 + a1) + (a2 + a3) + prev + bj);
        hslab[(size_t)t * BH + (size_t)b * HH + j0g + j] = v;

        grid_barrier(++barnum);
    }
}

// ---------------- tiny utility kernels ----------------
__global__ void init_kernel(const float* __restrict__ b_ih1,
                            const float* __restrict__ b_hh1)
{
    const int i = blockIdx.x * 256 + threadIdx.x;   // grid covers HH
    g_bias1c[i] = b_ih1[i] + b_hh1[i];
    if (i == 0) { g_arrive = 0u; g_release = 0u; }
}

__global__ void reset_barrier_kernel()
{
    g_arrive = 0u;
    g_release = 0u;
}

__global__ void __launch_bounds__(256) final_kernel(float* __restrict__ outh)
{
    const int i = blockIdx.x * 256 + threadIdx.x;   // grid covers BH
    outh[i]      = g_H0[(size_t)(SS - 1) * BH + i];
    outh[BH + i] = g_H1[(size_t)(SS - 1) * BH + i];
}

// ---------------- launcher ----------------
extern "C" void kernel_launch(void* const* d_in, const int* in_sizes, int n_in,
                              void* d_out, int out_size)
{
    const int*   inputs = (const int*)  d_in[0];  // [S,B]
    const float* hidden = (const float*)d_in[1];  // [L,B,H]
    const float* emb    = (const float*)d_in[2];  // [V,E]
    const float* W_ih   = (const float*)d_in[3];  // [L,H,E]
    const float* b_ih   = (const float*)d_in[4];  // [L,H]
    const float* W_hh   = (const float*)d_in[5];  // [L,H,H]
    const float* b_hh   = (const float*)d_in[6];  // [L,H]
    const float* W_out  = (const float*)d_in[7];  // [V,H]
    const float* b_out  = (const float*)d_in[8];  // [V]

    const float* W_ih0 = W_ih;
    const float* W_ih1 = W_ih + (size_t)HH * HH;
    const float* W_hh0 = W_hh;
    const float* W_hh1 = W_hh + (size_t)HH * HH;
    const float* b_ih0 = b_ih;
    const float* b_ih1 = b_ih + HH;
    const float* b_hh0 = b_hh;
    const float* b_hh1 = b_hh + HH;

    float *pre0, *pre1, *H0, *H1, *bias1c;
    cudaGetSymbolAddress((void**)&pre0,   g_pre0);
    cudaGetSymbolAddress((void**)&pre1,   g_pre1);
    cudaGetSymbolAddress((void**)&H0,     g_H0);
    cudaGetSymbolAddress((void**)&H1,     g_H1);
    cudaGetSymbolAddress((void**)&bias1c, g_bias1c);

    float* out = (float*)d_out;
    const long long logitsN = (long long)MM * VV;
    float* outh = ((long long)out_size >= logitsN + 2LL * BH) ? out + logitsN : nullptr;

    const int rec_smem = REC_SMEM_FLOATS * (int)sizeof(float);
    cudaFuncSetAttribute(rec_layer, cudaFuncAttributeMaxDynamicSharedMemorySize, rec_smem);

    // combined layer-1 bias + barrier reset (every replay)
    init_kernel<<<HH/256, 256>>>(b_ih1, b_hh1);

    // Phase A: pre0 = (emb[tok]*sqrt(E)) @ W_ih0^T + b_ih0
    {
        dim3 g(HH/128, MM/128);
        sgemm_tn<true><<<g, 256>>>(nullptr, emb, inputs, 32.0f,
                                   W_ih0, b_ih0, pre0, HH, HH, HH);
    }

    // Phase B0: layer-0 scan (adds b_hh0 inside)
    rec_layer<<<GRIDN, 512, rec_smem>>>(hidden, pre0, W_hh0, b_hh0, H0);

    // Phase A1: pre1 = H0all @ W_ih1^T + (b_ih1 + b_hh1)   (parallel over all steps)
    reset_barrier_kernel<<<1, 1>>>();
    {
        dim3 g(HH/128, MM/128);
        sgemm_tn<false><<<g, 256>>>(H0, nullptr, nullptr, 1.0f,
                                    W_ih1, bias1c, pre1, HH, HH, HH);
    }

    // Phase B1: layer-1 scan (biases already folded into pre1)
    rec_layer<<<GRIDN, 512, rec_smem>>>(hidden + BH, pre1, W_hh1, nullptr, H1);

    // Phase C: logits = H1all @ W_out^T + b_out
    {
        dim3 g((VV + 127) / 128, MM / 128);
        sgemm_tn<false><<<g, 256>>>(H1, nullptr, nullptr, 1.0f,
                                    W_out, b_out, out, VV, VV, HH);
    }

    // h_final = [h0(S-1), h1(S-1)]
    if (outh) final_kernel<<<BH/256, 256>>>(outh);
}

// round 6
// speedup vs baseline: 1.2305x; 1.2305x over previous
#include <cuda_runtime.h>
#include <cuda_bf16.h>
#include <math.h>

// Problem dims (fixed by the dataset)
#define SS 128      // sequence length
#define BB 64       // batch
#define HH 1024     // hidden = embedding dim
#define VV 10000    // vocab
#define MM (SS*BB)  // 8192 rows for the batched GEMMs
#define BH (BB*HH)  // 65536
#define GRIDN 128   // recurrence grid (128 j-tiles of 8)

// ---------------- device scratch (no allocations allowed) ----------------
// Hidden slabs are K-MAJOR per step: slab[t][k][b], with slab[0] = initial h.
__device__ __align__(16) float g_pre0[MM * HH];        // emb@W_ih0^T + b_ih0 (all steps), [t][b][j]
__device__ __align__(16) float g_pre1[MM * HH];        // H0@W_ih1^T + b_ih1 + b_hh1,     [t][b][j]
__device__ __align__(16) float g_H0[(SS + 1) * BH];    // layer-0 hidden slab [t][k][b]
__device__ __align__(16) float g_H1[(SS + 1) * BH];    // layer-1 hidden slab [t][k][b]
__device__ __align__(16) float g_bias1c[HH];           // b_ih1 + b_hh1
__device__ unsigned g_arrive;                          // grid barrier: arrival counter
__device__ unsigned g_release;                         // grid barrier: released generation

// ---------------- helpers ----------------
__device__ __forceinline__ unsigned ldcg_u(const unsigned* p) {
    unsigned v; asm volatile("ld.global.cg.u32 %0, [%1];" : "=r"(v) : "l"(p)); return v;
}
__device__ __forceinline__ unsigned smem_u32(const void* p) {
    unsigned a;
    asm("{ .reg .u64 t; cvta.to.shared.u64 t, %1; cvt.u32.u64 %0, t; }" : "=r"(a) : "l"(p));
    return a;
}
__device__ __forceinline__ void cp_async16(unsigned dst, const void* src) {
    asm volatile("cp.async.cg.shared.global [%0], [%1], 16;" :: "r"(dst), "l"(src));
}
__device__ __forceinline__ void cp_commit() {
    asm volatile("cp.async.commit_group;");
}
template<int N>
__device__ __forceinline__ void cp_wait() {
    asm volatile("cp.async.wait_group %0;" :: "n"(N));
}

// ---------------- grid-wide barrier (all GRIDN blocks resident) ----------
__device__ __forceinline__ void grid_barrier(unsigned want) {
    __syncthreads();
    if (threadIdx.x == 0) {
        __threadfence();
        unsigned prev = atomicAdd(&g_arrive, 1u);
        if (prev == want * GRIDN - 1u) {
            atomicExch(&g_release, want);
        }
        while (ldcg_u(&g_release) < want) { __nanosleep(32); }
    }
    __syncthreads();
}

// ---------------- generic tiled fp32 GEMM: C = A @ B^T + bias ----------------
// AMODE: 0 = A row-major [M][K]
//        1 = gather rows of emb via gidx, scaled
//        2 = scan-slab "column-major": A(m,k) = A[(m>>6)*BH + k*64 + (m&63)]
template<int AMODE>
__global__ void __launch_bounds__(256) sgemm_tn(
    const float* __restrict__ A,
    const float* __restrict__ emb,
    const int*   __restrict__ gidx,
    float scaleA,
    const float* __restrict__ Bm,
    const float* __restrict__ bias,
    float* __restrict__ C, int ldc,
    int N, int K)
{
    __shared__ float As[16][128 + 4];
    __shared__ float Bs[16][128 + 4];

    const int bm = blockIdx.y * 128;
    const int bn = blockIdx.x * 128;
    const int tid = threadIdx.x;
    const int tx = tid & 15;
    const int ty = tid >> 4;
    const int lr0 = tid >> 2;
    const int lr1 = lr0 + 64;
    const int lc4 = (tid & 3) * 4;

    const float* arow0 = nullptr;
    const float* arow1 = nullptr;
    if (AMODE == 1) {
        arow0 = emb + (size_t)gidx[bm + lr0] * K;
        arow1 = emb + (size_t)gidx[bm + lr1] * K;
    } else if (AMODE == 0) {
        arow0 = A + (size_t)(bm + lr0) * K;
        arow1 = A + (size_t)(bm + lr1) * K;
    }
    const int  bn0 = bn + lr0, bn1 = bn + lr1;
    const bool v0 = bn0 < N, v1 = bn1 < N;
    const float* brow0 = Bm + (size_t)bn0 * K;
    const float* brow1 = Bm + (size_t)bn1 * K;

    float acc[8][8] = {};

    for (int k0 = 0; k0 < K; k0 += 16) {
        if (AMODE == 2) {
            // slab tile: 16 k-rows x 128 m (two 64-wide b segments per 128)
            #pragma unroll
            for (int r = 0; r < 2; r++) {
                const int f  = tid + r * 256;      // 0..511 float4 slots
                const int kk = f >> 5;             // 0..15
                const int m0 = (f & 31) * 4;       // 0..124
                const float4 v = *(const float4*)&A[
                    (size_t)((bm + m0) >> 6) * BH + (size_t)(k0 + kk) * 64 + (m0 & 63)];
                As[kk][m0+0] = v.x; As[kk][m0+1] = v.y; As[kk][m0+2] = v.z; As[kk][m0+3] = v.w;
            }
        } else {
            float4 a0 = *(const float4*)(arow0 + k0 + lc4);
            float4 a1 = *(const float4*)(arow1 + k0 + lc4);
            if (AMODE == 1) {
                a0.x *= scaleA; a0.y *= scaleA; a0.z *= scaleA; a0.w *= scaleA;
                a1.x *= scaleA; a1.y *= scaleA; a1.z *= scaleA; a1.w *= scaleA;
            }
            As[lc4+0][lr0] = a0.x; As[lc4+1][lr0] = a0.y; As[lc4+2][lr0] = a0.z; As[lc4+3][lr0] = a0.w;
            As[lc4+0][lr1] = a1.x; As[lc4+1][lr1] = a1.y; As[lc4+2][lr1] = a1.z; As[lc4+3][lr1] = a1.w;
        }
        {
            float4 b0 = v0 ? *(const float4*)(brow0 + k0 + lc4) : make_float4(0.f,0.f,0.f,0.f);
            float4 b1 = v1 ? *(const float4*)(brow1 + k0 + lc4) : make_float4(0.f,0.f,0.f,0.f);
            Bs[lc4+0][lr0] = b0.x; Bs[lc4+1][lr0] = b0.y; Bs[lc4+2][lr0] = b0.z; Bs[lc4+3][lr0] = b0.w;
            Bs[lc4+0][lr1] = b1.x; Bs[lc4+1][lr1] = b1.y; Bs[lc4+2][lr1] = b1.z; Bs[lc4+3][lr1] = b1.w;
        }
        __syncthreads();

        #pragma unroll
        for (int kk = 0; kk < 16; kk++) {
            float4 av0 = *(const float4*)&As[kk][ty*8];
            float4 av1 = *(const float4*)&As[kk][ty*8 + 4];
            float4 bw0 = *(const float4*)&Bs[kk][tx*8];
            float4 bw1 = *(const float4*)&Bs[kk][tx*8 + 4];
            float a[8] = {av0.x, av0.y, av0.z, av0.w, av1.x, av1.y, av1.z, av1.w};
            float b[8] = {bw0.x, bw0.y, bw0.z, bw0.w, bw1.x, bw1.y, bw1.z, bw1.w};
            #pragma unroll
            for (int i = 0; i < 8; i++)
                #pragma unroll
                for (int j = 0; j < 8; j++)
                    acc[i][j] = fmaf(a[i], b[j], acc[i][j]);
        }
        __syncthreads();
    }

    #pragma unroll
    for (int i = 0; i < 8; i++) {
        const int m = bm + ty*8 + i;
        #pragma unroll
        for (int j = 0; j < 8; j++) {
            const int n = bn + tx*8 + j;
            if (n < N) C[(size_t)m * ldc + n] = acc[i][j] + bias[n];
        }
    }
}

// ---------------- single-layer recurrence scan (broadcast-W, k-major h) -----
// h(t) = tanh( pre[t] + h(t-1) @ W^T + bias )
// 128 blocks x 128 threads. Block owns 8 j (W tile 8x1024 SMEM-resident all steps).
// Warp w: j-pair (2w, 2w+1); lanes cover b and b+32 (2x2 register tile/thread).
// h(t-1) streamed k-major through double-buffered cp.async chunks of 256 k.
// SMEM: W 32KB + 2x64KB h buffers = 160KB. One grid barrier per step.
#define CHUNK2 256
#define REC_SMEM_FLOATS (8*1024 + 2*CHUNK2*64)

__global__ void __launch_bounds__(128, 1) rec_scan(
    const float* __restrict__ pre,    // [SS][B][H]
    const float* __restrict__ W,      // [H][H] row-major (row = out j)
    const float* __restrict__ bias,   // [H] or nullptr
    float* __restrict__ slab)         // [(SS+1)][H][B]; slab[0] = initial h
{
    extern __shared__ float sm[];
    float* Wsm = sm;                  // [8][1024]
    float* Hs  = sm + 8 * 1024;       // [2][CHUNK2*64]

    const int tid  = threadIdx.x;
    const int w    = tid >> 5;
    const int lane = tid & 31;
    const int j0g  = blockIdx.x * 8;
    const int jl0  = w * 2, jl1 = w * 2 + 1;

    // one-time W tile: 8 x 1024 = 2048 float4, 16 per thread
    #pragma unroll
    for (int r = 0; r < 16; r++) {
        const int idx = tid + r * 128;
        const int jr = idx >> 8, f4 = idx & 255;
        *(float4*)&Wsm[jr * 1024 + f4 * 4] =
            *(const float4*)&W[(size_t)(j0g + jr) * HH + f4 * 4];
    }
    const float bj0 = bias ? bias[j0g + jl0] : 0.0f;
    const float bj1 = bias ? bias[j0g + jl1] : 0.0f;
    __syncthreads();

    const unsigned hsb = smem_u32(Hs);
    const float* w0base = Wsm + jl0 * 1024;
    const float* w1base = Wsm + jl1 * 1024;

    unsigned barnum = 0;

    for (int t = 0; t < SS; t++) {
        const float* hsrc = slab + (size_t)t * BH;   // h(t-1), k-major [k][b]

        // drive terms (prefetch early; L1-cacheable, pre is immutable here)
        const size_t pb = (size_t)t * BH;
        const float p00 = __ldg(&pre[pb + (size_t)lane * HH + j0g + jl0]);
        const float p01 = __ldg(&pre[pb + (size_t)lane * HH + j0g + jl1]);
        const float p10 = __ldg(&pre[pb + (size_t)(lane + 32) * HH + j0g + jl0]);
        const float p11 = __ldg(&pre[pb + (size_t)(lane + 32) * HH + j0g + jl1]);

        // stage chunk 0 (pure linear copy: 64KB = 4096 float4, 32/thread)
        #pragma unroll
        for (int r = 0; r < 32; r++) {
            const int idx = tid + r * 128;
            cp_async16(hsb + (unsigned)idx * 16u, hsrc + (size_t)idx * 4);
        }
        cp_commit();

        float a00 = 0.f, a01 = 0.f, a10 = 0.f, a11 = 0.f;

        #pragma unroll
        for (int c = 0; c < 4; c++) {
            if (c < 3) {
                const unsigned buf = (unsigned)((c + 1) & 1) * CHUNK2 * 64u * 4u;
                const float* src = hsrc + (size_t)(c + 1) * CHUNK2 * 64;
                #pragma unroll
                for (int r = 0; r < 32; r++) {
                    const int idx = tid + r * 128;
                    cp_async16(hsb + buf + (unsigned)idx * 16u, src + (size_t)idx * 4);
                }
                cp_commit();
                cp_wait<1>();
            } else {
                cp_wait<0>();
            }
            __syncthreads();

            const float* hb = Hs + (c & 1) * CHUNK2 * 64;
            const float* wc0 = w0base + c * CHUNK2;
            const float* wc1 = w1base + c * CHUNK2;
            #pragma unroll 8
            for (int k = 0; k < CHUNK2; k += 4) {
                const float4 wv0 = *(const float4*)&wc0[k];   // broadcast within warp
                const float4 wv1 = *(const float4*)&wc1[k];
                const float h00 = hb[(k+0)*64 + lane];
                const float h01 = hb[(k+1)*64 + lane];
                const float h02 = hb[(k+2)*64 + lane];
                const float h03 = hb[(k+3)*64 + lane];
                const float h10 = hb[(k+0)*64 + lane + 32];
                const float h11 = hb[(k+1)*64 + lane + 32];
                const float h12 = hb[(k+2)*64 + lane + 32];
                const float h13 = hb[(k+3)*64 + lane + 32];
                a00 = fmaf(h00, wv0.x, a00); a00 = fmaf(h01, wv0.y, a00);
                a00 = fmaf(h02, wv0.z, a00); a00 = fmaf(h03, wv0.w, a00);
                a01 = fmaf(h00, wv1.x, a01); a01 = fmaf(h01, wv1.y, a01);
                a01 = fmaf(h02, wv1.z, a01); a01 = fmaf(h03, wv1.w, a01);
                a10 = fmaf(h10, wv0.x, a10); a10 = fmaf(h11, wv0.y, a10);
                a10 = fmaf(h12, wv0.z, a10); a10 = fmaf(h13, wv0.w, a10);
                a11 = fmaf(h10, wv1.x, a11); a11 = fmaf(h11, wv1.y, a11);
                a11 = fmaf(h12, wv1.z, a11); a11 = fmaf(h13, wv1.w, a11);
            }
            __syncthreads();
        }

        // activation + k-major store of h(t)
        float* dst = slab + (size_t)(t + 1) * BH;
        dst[(size_t)(j0g + jl0) * 64 + lane]      = tanhf(a00 + p00 + bj0);
        dst[(size_t)(j0g + jl1) * 64 + lane]      = tanhf(a01 + p01 + bj1);
        dst[(size_t)(j0g + jl0) * 64 + lane + 32] = tanhf(a10 + p10 + bj0);
        dst[(size_t)(j0g + jl1) * 64 + lane + 32] = tanhf(a11 + p11 + bj1);

        grid_barrier(++barnum);
    }
}

// ---------------- tiny utility kernels ----------------
// bias1c + barrier reset
__global__ void init_kernel(const float* __restrict__ b_ih1,
                            const float* __restrict__ b_hh1)
{
    const int i = blockIdx.x * 256 + threadIdx.x;   // grid covers HH
    g_bias1c[i] = b_ih1[i] + b_hh1[i];
    if (i == 0) { g_arrive = 0u; g_release = 0u; }
}

// transpose initial hidden [b][k] -> slab[0] [k][b]; optional barrier reset
__global__ void __launch_bounds__(256) init_slab(
    const float* __restrict__ hsrc, float* __restrict__ slab0, int reset)
{
    const int i = blockIdx.x * 256 + threadIdx.x;   // grid covers BH
    const int k = i >> 6, b = i & 63;
    slab0[i] = hsrc[(size_t)b * HH + k];
    if (i == 0 && reset) { g_arrive = 0u; g_release = 0u; }
}

// final hidden: outh[l][b][j] from slab[SS] (k-major)
__global__ void __launch_bounds__(256) final_kernel(float* __restrict__ outh)
{
    const int i = blockIdx.x * 256 + threadIdx.x;   // grid covers BH
    const int b = i >> 10, j = i & (HH - 1);
    outh[i]      = g_H0[(size_t)SS * BH + (size_t)j * 64 + b];
    outh[BH + i] = g_H1[(size_t)SS * BH + (size_t)j * 64 + b];
}

// ---------------- launcher ----------------
extern "C" void kernel_launch(void* const* d_in, const int* in_sizes, int n_in,
                              void* d_out, int out_size)
{
    const int*   inputs = (const int*)  d_in[0];  // [S,B]
    const float* hidden = (const float*)d_in[1];  // [L,B,H]
    const float* emb    = (const float*)d_in[2];  // [V,E]
    const float* W_ih   = (const float*)d_in[3];  // [L,H,E]
    const float* b_ih   = (const float*)d_in[4];  // [L,H]
    const float* W_hh   = (const float*)d_in[5];  // [L,H,H]
    const float* b_hh   = (const float*)d_in[6];  // [L,H]
    const float* W_out  = (const float*)d_in[7];  // [V,H]
    const float* b_out  = (const float*)d_in[8];  // [V]

    const float* W_ih0 = W_ih;
    const float* W_ih1 = W_ih + (size_t)HH * HH;
    const float* W_hh0 = W_hh;
    const float* W_hh1 = W_hh + (size_t)HH * HH;
    const float* b_ih1 = b_ih + HH;
    const float* b_hh0 = b_hh;
    const float* b_hh1 = b_hh + HH;
    const float* b_ih0 = b_ih;

    float *pre0, *pre1, *H0, *H1, *bias1c;
    cudaGetSymbolAddress((void**)&pre0,   g_pre0);
    cudaGetSymbolAddress((void**)&pre1,   g_pre1);
    cudaGetSymbolAddress((void**)&H0,     g_H0);
    cudaGetSymbolAddress((void**)&H1,     g_H1);
    cudaGetSymbolAddress((void**)&bias1c, g_bias1c);

    float* out = (float*)d_out;
    const long long logitsN = (long long)MM * VV;
    float* outh = ((long long)out_size >= logitsN + 2LL * BH) ? out + logitsN : nullptr;

    const int rec_smem = REC_SMEM_FLOATS * (int)sizeof(float);
    cudaFuncSetAttribute(rec_scan, cudaFuncAttributeMaxDynamicSharedMemorySize, rec_smem);

    // bias1c + barrier reset (every replay)
    init_kernel<<<HH/256, 256>>>(b_ih1, b_hh1);

    // Phase A: pre0 = (emb[tok]*sqrt(E)) @ W_ih0^T + b_ih0
    {
        dim3 g(HH/128, MM/128);
        sgemm_tn<1><<<g, 256>>>(nullptr, emb, inputs, 32.0f,
                                W_ih0, b_ih0, pre0, HH, HH, HH);
    }

    // layer-0 initial hidden -> H0 slab[0] (k-major)
    init_slab<<<BH/256, 256>>>(hidden, H0, 0);

    // Phase B0: layer-0 scan
    rec_scan<<<GRIDN, 128, rec_smem>>>(pre0, W_hh0, b_hh0, H0);

    // layer-1 initial hidden -> H1 slab[0]; reset barrier for second scan
    init_slab<<<BH/256, 256>>>(hidden + BH, H1, 1);

    // Phase A1: pre1 = H0(all steps) @ W_ih1^T + (b_ih1 + b_hh1)
    {
        dim3 g(HH/128, MM/128);
        sgemm_tn<2><<<g, 256>>>(H0 + BH, nullptr, nullptr, 1.0f,
                                W_ih1, bias1c, pre1, HH, HH, HH);
    }

    // Phase B1: layer-1 scan (biases folded into pre1)
    rec_scan<<<GRIDN, 128, rec_smem>>>(pre1, W_hh1, nullptr, H1);

    // Phase C: logits = H1(all steps) @ W_out^T + b_out
    {
        dim3 g((VV + 127) / 128, MM / 128);
        sgemm_tn<2><<<g, 256>>>(H1 + BH, nullptr, nullptr, 1.0f,
                                W_out, b_out, out, VV, VV, HH);
    }

    // h_final = [h0(S-1), h1(S-1)]
    if (outh) final_kernel<<<BH/256, 256>>>(outh);
}

// round 8
// speedup vs baseline: 1.7002x; 1.3818x over previous
#include <cuda_runtime.h>
#include <cuda_bf16.h>
#include <math.h>
#include <stdint.h>

// Problem dims (fixed by the dataset)
#define SS 128      // sequence length
#define BB 64       // batch
#define HH 1024     // hidden = embedding dim
#define VV 10000    // vocab
#define MM (SS*BB)  // 8192 rows for the batched GEMMs
#define BH (BB*HH)  // 65536
#define GRIDN 128   // recurrence grid
#define NPAD 10240  // vocab padded to 128-multiple for tensor tiles

// ---------------- device scratch (no allocations allowed) ----------------
__device__ __align__(16) float g_pre0[MM * HH];        // drive terms layer 0, [t][b][j]
__device__ __align__(16) float g_pre1[MM * HH];        // drive terms layer 1, [t][b][j]
__device__ __align__(16) float g_H0[(SS + 1) * BH];    // layer-0 hidden slab [t][k][b]
__device__ __align__(16) float g_H1[(SS + 1) * BH];    // layer-1 hidden slab [t][k][b]
__device__ __align__(16) float g_bias1c[HH];           // b_ih1 + b_hh1
__device__ __align__(16) __nv_bfloat16 g_Ahi[MM * HH];   // split-bf16 A (hi)
__device__ __align__(16) __nv_bfloat16 g_Alo[MM * HH];   // split-bf16 A (lo)
__device__ __align__(16) __nv_bfloat16 g_Bhi[NPAD * HH]; // split-bf16 B (hi)
__device__ __align__(16) __nv_bfloat16 g_Blo[NPAD * HH]; // split-bf16 B (lo)
__device__ unsigned g_arrive;                          // grid barrier: arrival counter
__device__ unsigned g_release;                         // grid barrier: released generation

// ---------------- generic helpers ----------------
__device__ __forceinline__ unsigned ldcg_u(const unsigned* p) {
    unsigned v; asm volatile("ld.global.cg.u32 %0, [%1];" : "=r"(v) : "l"(p)); return v;
}
__device__ __forceinline__ unsigned smem_u32(const void* p) {
    unsigned a;
    asm("{ .reg .u64 t; cvta.to.shared.u64 t, %1; cvt.u32.u64 %0, t; }" : "=r"(a) : "l"(p));
    return a;
}
__device__ __forceinline__ void cp_async16(unsigned dst, const void* src) {
    asm volatile("cp.async.cg.shared.global [%0], [%1], 16;" :: "r"(dst), "l"(src));
}
__device__ __forceinline__ void cp_commit() {
    asm volatile("cp.async.commit_group;");
}
template<int N>
__device__ __forceinline__ void cp_wait() {
    asm volatile("cp.async.wait_group %0;" :: "n"(N));
}

// ---------------- grid-wide barrier (all GRIDN blocks resident) ----------
__device__ __forceinline__ void grid_barrier(unsigned want) {
    __syncthreads();
    if (threadIdx.x == 0) {
        __threadfence();
        unsigned prev = atomicAdd(&g_arrive, 1u);
        if (prev == want * GRIDN - 1u) {
            atomicExch(&g_release, want);
        }
        while (ldcg_u(&g_release) < want) { __nanosleep(32); }
    }
    __syncthreads();
}

// ---------------- split-bf16 helpers ----------------
__device__ __forceinline__ void split4_store(float4 v,
    __nv_bfloat16* hi, __nv_bfloat16* lo, size_t off)
{
    float vv[4] = {v.x, v.y, v.z, v.w};
    uint32_t ph[2], pl[2];
    #pragma unroll
    for (int e = 0; e < 2; e++) {
        __nv_bfloat16 h0 = __float2bfloat16(vv[e*2+0]);
        __nv_bfloat16 h1 = __float2bfloat16(vv[e*2+1]);
        __nv_bfloat16 l0 = __float2bfloat16(vv[e*2+0] - __bfloat162float(h0));
        __nv_bfloat16 l1 = __float2bfloat16(vv[e*2+1] - __bfloat162float(h1));
        __nv_bfloat162 hh; hh.x = h0; hh.y = h1; ph[e] = *(uint32_t*)&hh;
        __nv_bfloat162 ll; ll.x = l0; ll.y = l1; pl[e] = *(uint32_t*)&ll;
    }
    *(uint2*)(hi + off) = make_uint2(ph[0], ph[1]);
    *(uint2*)(lo + off) = make_uint2(pl[0], pl[1]);
}

// weights [Nrows][K] -> hi/lo, zero-padded rows up to grid coverage
__global__ void __launch_bounds__(256) conv_w(
    const float* __restrict__ W, int Nrows,
    __nv_bfloat16* __restrict__ hi, __nv_bfloat16* __restrict__ lo)
{
    const int idx = blockIdx.x * 256 + threadIdx.x;   // over Npad*(K/4)
    const int row = idx >> 8;
    const int c4  = (idx & 255) * 4;
    float4 v = make_float4(0.f, 0.f, 0.f, 0.f);
    if (row < Nrows) v = *(const float4*)&W[(size_t)row * HH + c4];
    split4_store(v, hi, lo, (size_t)row * HH + c4);
}

// gathered, scaled embedding -> hi/lo A slab [m][K]
__global__ void __launch_bounds__(256) conv_gather(
    const int* __restrict__ gidx, const float* __restrict__ emb,
    __nv_bfloat16* __restrict__ hi, __nv_bfloat16* __restrict__ lo)
{
    const int idx = blockIdx.x * 256 + threadIdx.x;   // over MM*(K/4)
    const int m  = idx >> 8;
    const int c4 = (idx & 255) * 4;
    float4 v = *(const float4*)&emb[(size_t)gidx[m] * HH + c4];
    v.x *= 32.f; v.y *= 32.f; v.z *= 32.f; v.w *= 32.f;
    split4_store(v, hi, lo, (size_t)m * HH + c4);
}

// hidden slab [t][k][b] -> hi/lo A slab [m=t*64+b][k] (transpose via SMEM)
__global__ void __launch_bounds__(256) conv_slab(
    const float* __restrict__ slab,
    __nv_bfloat16* __restrict__ hi, __nv_bfloat16* __restrict__ lo)
{
    __shared__ float s[64][65];
    const int t  = blockIdx.x >> 4;
    const int k0 = (blockIdx.x & 15) * 64;
    const int tid = threadIdx.x;
    #pragma unroll
    for (int r = 0; r < 16; r++) {
        const int idx = tid + r * 256;       // 0..4095
        const int kk = idx >> 6, b = idx & 63;
        s[kk][b] = slab[(size_t)t * BH + (size_t)(k0 + kk) * 64 + b];
    }
    __syncthreads();
    const int b   = tid >> 2;
    const int seg = (tid & 3) * 16;
    const size_t base = (size_t)(t * 64 + b) * HH + k0 + seg;
    #pragma unroll
    for (int q = 0; q < 4; q++) {
        float4 v = make_float4(s[seg + q*4 + 0][b], s[seg + q*4 + 1][b],
                               s[seg + q*4 + 2][b], s[seg + q*4 + 3][b]);
        split4_store(v, hi, lo, base + q * 4);
    }
}

// ---------------- mma.sync bf16 split GEMM: C = A@B^T + bias ----------------
// Baseline PTX (sm_80+) — works on unsuffixed compute_103 target.
// Tile 128x128, BK=32 bf16, 256 threads = 8 warps (2M x 4N), warp tile 64x32.
// K' = 3*1024: segments (Ah,Bh), (Ah,Bl), (Al,Bh) accumulated in fp32.
#define BKC   32
#define TSTR  40                    // padded row stride in bf16 (80B: conflict-free ldmatrix)
#define NCHK  96                    // 3 segments x 32 chunks

__device__ __forceinline__ void ldm_x4(uint32_t* r, uint32_t addr) {
    asm volatile("ldmatrix.sync.aligned.m8n8.x4.shared.b16 {%0,%1,%2,%3}, [%4];"
                 : "=r"(r[0]), "=r"(r[1]), "=r"(r[2]), "=r"(r[3]) : "r"(addr));
}
__device__ __forceinline__ void mma16816(float* c, const uint32_t* a, const uint32_t* b) {
    asm volatile(
        "mma.sync.aligned.m16n8k16.row.col.f32.bf16.bf16.f32 "
        "{%0,%1,%2,%3}, {%4,%5,%6,%7}, {%8,%9}, {%0,%1,%2,%3};"
        : "+f"(c[0]), "+f"(c[1]), "+f"(c[2]), "+f"(c[3])
        : "r"(a[0]), "r"(a[1]), "r"(a[2]), "r"(a[3]), "r"(b[0]), "r"(b[1]));
}

__global__ void __launch_bounds__(256, 1) hmma_gemm(
    const __nv_bfloat16* __restrict__ Ahi, const __nv_bfloat16* __restrict__ Alo,
    const __nv_bfloat16* __restrict__ Bhi, const __nv_bfloat16* __restrict__ Blo,
    const float* __restrict__ bias, float* __restrict__ C, int ldc, int Nvalid)
{
    __shared__ __nv_bfloat16 As[2][128 * TSTR];
    __shared__ __nv_bfloat16 Bs[2][128 * TSTR];

    const int tid  = threadIdx.x;
    const int wrp  = tid >> 5;
    const int lane = tid & 31;
    const int wm   = (wrp >> 2) * 64;    // warp M offset
    const int wn   = (wrp & 3) * 32;     // warp N offset
    const int bm   = blockIdx.y * 128;
    const int bn   = blockIdx.x * 128;

    const uint32_t as_base = smem_u32(&As[0][0]);
    const uint32_t bs_base = smem_u32(&Bs[0][0]);
    const uint32_t bufstride = 128u * TSTR * 2u;

    // ldmatrix per-lane smem addresses (byte offsets within a buffer)
    // A tiles (16x16): row = wm + mt*16 + (lane&15), col = ks*16 + (lane>>4)*8
    const uint32_t a_row = (uint32_t)(wm + (lane & 15));
    const uint32_t a_col = (uint32_t)((lane >> 4) * 8);
    // B tiles (x4 covers two n8k16 frags): row = wn + np*16 + (lane>>4)*8 + (lane&7),
    //                                      col = ks*16 + ((lane>>3)&1)*8
    const uint32_t b_row = (uint32_t)(wn + ((lane >> 4) * 8) + (lane & 7));
    const uint32_t b_col = (uint32_t)(((lane >> 3) & 1) * 8);

    float acc[4][4][4] = {};   // [mt][nt][frag]

    // global load thread mapping: 512 16B-chunks per operand per stage
    const int g_row = tid >> 1;           // 0..127 (2 threads per row)
    const int g_c   = (tid & 1) * 2;      // 16B-chunk pair start (0 or 2)

    // ---- prologue: stage chunk 0 (segment 0: Ah, Bh)
    {
        const __nv_bfloat16* Ap = Ahi + (size_t)(bm + g_row) * HH;
        const __nv_bfloat16* Bp = Bhi + (size_t)(bn + g_row) * HH;
        const uint32_t da = as_base + (uint32_t)(g_row * TSTR * 2) + (uint32_t)g_c * 16u;
        const uint32_t db = bs_base + (uint32_t)(g_row * TSTR * 2) + (uint32_t)g_c * 16u;
        cp_async16(da,       Ap + g_c * 8);
        cp_async16(da + 16u, Ap + g_c * 8 + 8);
        cp_async16(db,       Bp + g_c * 8);
        cp_async16(db + 16u, Bp + g_c * 8 + 8);
        cp_commit();
    }

    for (int c = 0; c < NCHK; c++) {
        if (c + 1 < NCHK) {
            const int nc  = c + 1;
            const int seg = nc >> 5;
            const int kk  = (nc & 31) * BKC;
            const __nv_bfloat16* Asrc = (seg == 2) ? Alo : Ahi;
            const __nv_bfloat16* Bsrc = (seg == 1) ? Blo : Bhi;
            const uint32_t boff = (uint32_t)(nc & 1) * bufstride;
            const __nv_bfloat16* Ap = Asrc + (size_t)(bm + g_row) * HH + kk;
            const __nv_bfloat16* Bp = Bsrc + (size_t)(bn + g_row) * HH + kk;
            const uint32_t da = as_base + boff + (uint32_t)(g_row * TSTR * 2) + (uint32_t)g_c * 16u;
            const uint32_t db = bs_base + boff + (uint32_t)(g_row * TSTR * 2) + (uint32_t)g_c * 16u;
            cp_async16(da,       Ap + g_c * 8);
            cp_async16(da + 16u, Ap + g_c * 8 + 8);
            cp_async16(db,       Bp + g_c * 8);
            cp_async16(db + 16u, Bp + g_c * 8 + 8);
            cp_commit();
            cp_wait<1>();
        } else {
            cp_wait<0>();
        }
        __syncthreads();

        const uint32_t boff = (uint32_t)(c & 1) * bufstride;
        #pragma unroll
        for (int ks = 0; ks < 2; ks++) {
            uint32_t a[4][4], b[2][4];
            #pragma unroll
            for (int mt = 0; mt < 4; mt++) {
                const uint32_t addr = as_base + boff +
                    ((a_row + mt * 16u) * TSTR + a_col + (uint32_t)ks * 16u) * 2u;
                ldm_x4(a[mt], addr);
            }
            #pragma unroll
            for (int np = 0; np < 2; np++) {
                const uint32_t addr = bs_base + boff +
                    ((b_row + np * 16u) * TSTR + b_col + (uint32_t)ks * 16u) * 2u;
                ldm_x4(b[np], addr);
            }
            #pragma unroll
            for (int mt = 0; mt < 4; mt++) {
                #pragma unroll
                for (int nt = 0; nt < 4; nt++) {
                    // nt -> (np = nt>>1, pair = nt&1): regs {b[np][2*pair], b[np][2*pair+1]}
                    uint32_t bb[2] = { b[nt >> 1][(nt & 1) * 2],
                                       b[nt >> 1][(nt & 1) * 2 + 1] };
                    mma16816(acc[mt][nt], a[mt], bb);
                }
            }
        }
        __syncthreads();
    }

    // ---- epilogue: D[m][n] + bias[n]
    const int er = lane >> 2;          // 0..7
    const int ec = (lane & 3) * 2;     // 0,2,4,6
    #pragma unroll
    for (int mt = 0; mt < 4; mt++) {
        const int m0 = bm + wm + mt * 16 + er;
        #pragma unroll
        for (int nt = 0; nt < 4; nt++) {
            const int n0 = bn + wn + nt * 8 + ec;
            if (n0 + 1 < Nvalid) {
                const float bz0 = __ldg(&bias[n0]);
                const float bz1 = __ldg(&bias[n0 + 1]);
                *(float2*)&C[(size_t)m0 * ldc + n0] =
                    make_float2(acc[mt][nt][0] + bz0, acc[mt][nt][1] + bz1);
                *(float2*)&C[(size_t)(m0 + 8) * ldc + n0] =
                    make_float2(acc[mt][nt][2] + bz0, acc[mt][nt][3] + bz1);
            } else if (n0 < Nvalid) {
                const float bz0 = __ldg(&bias[n0]);
                C[(size_t)m0 * ldc + n0]       = acc[mt][nt][0] + bz0;
                C[(size_t)(m0 + 8) * ldc + n0] = acc[mt][nt][2] + bz0;
            }
        }
    }
}

// ---------------- single-layer recurrence scan (R6, unchanged) --------------
#define CHUNK2 256
#define REC_SMEM_FLOATS (8*1024 + 2*CHUNK2*64)

__global__ void __launch_bounds__(128, 1) rec_scan(
    const float* __restrict__ pre,    // [SS][B][H]
    const float* __restrict__ W,      // [H][H] row-major (row = out j)
    const float* __restrict__ bias,   // [H] or nullptr
    float* __restrict__ slab)         // [(SS+1)][H][B]; slab[0] = initial h
{
    extern __shared__ float sm[];
    float* Wsm = sm;                  // [8][1024]
    float* Hs  = sm + 8 * 1024;       // [2][CHUNK2*64]

    const int tid  = threadIdx.x;
    const int w    = tid >> 5;
    const int lane = tid & 31;
    const int j0g  = blockIdx.x * 8;
    const int jl0  = w * 2, jl1 = w * 2 + 1;

    #pragma unroll
    for (int r = 0; r < 16; r++) {
        const int idx = tid + r * 128;
        const int jr = idx >> 8, f4 = idx & 255;
        *(float4*)&Wsm[jr * 1024 + f4 * 4] =
            *(const float4*)&W[(size_t)(j0g + jr) * HH + f4 * 4];
    }
    const float bj0 = bias ? bias[j0g + jl0] : 0.0f;
    const float bj1 = bias ? bias[j0g + jl1] : 0.0f;
    __syncthreads();

    const unsigned hsb = smem_u32(Hs);
    const float* w0base = Wsm + jl0 * 1024;
    const float* w1base = Wsm + jl1 * 1024;

    unsigned barnum = 0;

    for (int t = 0; t < SS; t++) {
        const float* hsrc = slab + (size_t)t * BH;

        const size_t pb = (size_t)t * BH;
        const float p00 = __ldg(&pre[pb + (size_t)lane * HH + j0g + jl0]);
        const float p01 = __ldg(&pre[pb + (size_t)lane * HH + j0g + jl1]);
        const float p10 = __ldg(&pre[pb + (size_t)(lane + 32) * HH + j0g + jl0]);
        const float p11 = __ldg(&pre[pb + (size_t)(lane + 32) * HH + j0g + jl1]);

        #pragma unroll
        for (int r = 0; r < 32; r++) {
            const int idx = tid + r * 128;
            cp_async16(hsb + (unsigned)idx * 16u, hsrc + (size_t)idx * 4);
        }
        cp_commit();

        float a00 = 0.f, a01 = 0.f, a10 = 0.f, a11 = 0.f;

        #pragma unroll
        for (int c = 0; c < 4; c++) {
            if (c < 3) {
                const unsigned buf = (unsigned)((c + 1) & 1) * CHUNK2 * 64u * 4u;
                const float* src = hsrc + (size_t)(c + 1) * CHUNK2 * 64;
                #pragma unroll
                for (int r = 0; r < 32; r++) {
                    const int idx = tid + r * 128;
                    cp_async16(hsb + buf + (unsigned)idx * 16u, src + (size_t)idx * 4);
                }
                cp_commit();
                cp_wait<1>();
            } else {
                cp_wait<0>();
            }
            __syncthreads();

            const float* hb = Hs + (c & 1) * CHUNK2 * 64;
            const float* wc0 = w0base + c * CHUNK2;
            const float* wc1 = w1base + c * CHUNK2;
            #pragma unroll 8
            for (int k = 0; k < CHUNK2; k += 4) {
                const float4 wv0 = *(const float4*)&wc0[k];
                const float4 wv1 = *(const float4*)&wc1[k];
                const float h00 = hb[(k+0)*64 + lane];
                const float h01 = hb[(k+1)*64 + lane];
                const float h02 = hb[(k+2)*64 + lane];
                const float h03 = hb[(k+3)*64 + lane];
                const float h10 = hb[(k+0)*64 + lane + 32];
                const float h11 = hb[(k+1)*64 + lane + 32];
                const float h12 = hb[(k+2)*64 + lane + 32];
                const float h13 = hb[(k+3)*64 + lane + 32];
                a00 = fmaf(h00, wv0.x, a00); a00 = fmaf(h01, wv0.y, a00);
                a00 = fmaf(h02, wv0.z, a00); a00 = fmaf(h03, wv0.w, a00);
                a01 = fmaf(h00, wv1.x, a01); a01 = fmaf(h01, wv1.y, a01);
                a01 = fmaf(h02, wv1.z, a01); a01 = fmaf(h03, wv1.w, a01);
                a10 = fmaf(h10, wv0.x, a10); a10 = fmaf(h11, wv0.y, a10);
                a10 = fmaf(h12, wv0.z, a10); a10 = fmaf(h13, wv0.w, a10);
                a11 = fmaf(h10, wv1.x, a11); a11 = fmaf(h11, wv1.y, a11);
                a11 = fmaf(h12, wv1.z, a11); a11 = fmaf(h13, wv1.w, a11);
            }
            __syncthreads();
        }

        float* dst = slab + (size_t)(t + 1) * BH;
        dst[(size_t)(j0g + jl0) * 64 + lane]      = tanhf(a00 + p00 + bj0);
        dst[(size_t)(j0g + jl1) * 64 + lane]      = tanhf(a01 + p01 + bj1);
        dst[(size_t)(j0g + jl0) * 64 + lane + 32] = tanhf(a10 + p10 + bj0);
        dst[(size_t)(j0g + jl1) * 64 + lane + 32] = tanhf(a11 + p11 + bj1);

        grid_barrier(++barnum);
    }
}

// ---------------- tiny utility kernels ----------------
__global__ void init_kernel(const float* __restrict__ b_ih1,
                            const float* __restrict__ b_hh1)
{
    const int i = blockIdx.x * 256 + threadIdx.x;   // grid covers HH
    g_bias1c[i] = b_ih1[i] + b_hh1[i];
    if (i == 0) { g_arrive = 0u; g_release = 0u; }
}

__global__ void __launch_bounds__(256) init_slab(
    const float* __restrict__ hsrc, float* __restrict__ slab0, int reset)
{
    const int i = blockIdx.x * 256 + threadIdx.x;   // grid covers BH
    const int k = i >> 6, b = i & 63;
    slab0[i] = hsrc[(size_t)b * HH + k];
    if (i == 0 && reset) { g_arrive = 0u; g_release = 0u; }
}

__global__ void __launch_bounds__(256) final_kernel(float* __restrict__ outh)
{
    const int i = blockIdx.x * 256 + threadIdx.x;   // grid covers BH
    const int b = i >> 10, j = i & (HH - 1);
    outh[i]      = g_H0[(size_t)SS * BH + (size_t)j * 64 + b];
    outh[BH + i] = g_H1[(size_t)SS * BH + (size_t)j * 64 + b];
}

// ---------------- launcher ----------------
extern "C" void kernel_launch(void* const* d_in, const int* in_sizes, int n_in,
                              void* d_out, int out_size)
{
    const int*   inputs = (const int*)  d_in[0];  // [S,B]
    const float* hidden = (const float*)d_in[1];  // [L,B,H]
    const float* emb    = (const float*)d_in[2];  // [V,E]
    const float* W_ih   = (const float*)d_in[3];  // [L,H,E]
    const float* b_ih   = (const float*)d_in[4];  // [L,H]
    const float* W_hh   = (const float*)d_in[5];  // [L,H,H]
    const float* b_hh   = (const float*)d_in[6];  // [L,H]
    const float* W_out  = (const float*)d_in[7];  // [V,H]
    const float* b_out  = (const float*)d_in[8];  // [V]

    const float* W_ih0 = W_ih;
    const float* W_ih1 = W_ih + (size_t)HH * HH;
    const float* W_hh0 = W_hh;
    const float* W_hh1 = W_hh + (size_t)HH * HH;
    const float* b_ih0 = b_ih;
    const float* b_ih1 = b_ih + HH;
    const float* b_hh0 = b_hh;
    const float* b_hh1 = b_hh + HH;

    float *pre0, *pre1, *H0, *H1, *bias1c;
    __nv_bfloat16 *Ahi, *Alo, *Bhi, *Blo;
    cudaGetSymbolAddress((void**)&pre0,   g_pre0);
    cudaGetSymbolAddress((void**)&pre1,   g_pre1);
    cudaGetSymbolAddress((void**)&H0,     g_H0);
    cudaGetSymbolAddress((void**)&H1,     g_H1);
    cudaGetSymbolAddress((void**)&bias1c, g_bias1c);
    cudaGetSymbolAddress((void**)&Ahi,    g_Ahi);
    cudaGetSymbolAddress((void**)&Alo,    g_Alo);
    cudaGetSymbolAddress((void**)&Bhi,    g_Bhi);
    cudaGetSymbolAddress((void**)&Blo,    g_Blo);

    float* out = (float*)d_out;
    const long long logitsN = (long long)MM * VV;
    float* outh = ((long long)out_size >= logitsN + 2LL * BH) ? out + logitsN : nullptr;

    const int rec_smem = REC_SMEM_FLOATS * (int)sizeof(float);
    cudaFuncSetAttribute(rec_scan, cudaFuncAttributeMaxDynamicSharedMemorySize, rec_smem);

    // bias1c + barrier reset
    init_kernel<<<HH/256, 256>>>(b_ih1, b_hh1);

    // Phase A (mma.sync bf16 split): pre0 = (emb[tok]*32) @ W_ih0^T + b_ih0
    conv_gather<<<MM, 256>>>(inputs, emb, Ahi, Alo);
    conv_w<<<HH, 256>>>(W_ih0, HH, Bhi, Blo);
    {
        dim3 g(HH/128, MM/128);
        hmma_gemm<<<g, 256>>>(Ahi, Alo, Bhi, Blo, b_ih0, pre0, HH, HH);
    }

    // layer-0 scan
    init_slab<<<BH/256, 256>>>(hidden, H0, 0);
    rec_scan<<<GRIDN, 128, rec_smem>>>(pre0, W_hh0, b_hh0, H0);

    // Phase A1: pre1 = H0all @ W_ih1^T + (b_ih1 + b_hh1)
    conv_slab<<<SS*16, 256>>>(H0 + BH, Ahi, Alo);
    conv_w<<<HH, 256>>>(W_ih1, HH, Bhi, Blo);
    init_slab<<<BH/256, 256>>>(hidden + BH, H1, 1);   // also resets grid barrier
    {
        dim3 g(HH/128, MM/128);
        hmma_gemm<<<g, 256>>>(Ahi, Alo, Bhi, Blo, bias1c, pre1, HH, HH);
    }

    // layer-1 scan
    rec_scan<<<GRIDN, 128, rec_smem>>>(pre1, W_hh1, nullptr, H1);

    // Phase C: logits = H1all @ W_out^T + b_out
    conv_slab<<<SS*16, 256>>>(H1 + BH, Ahi, Alo);
    conv_w<<<NPAD, 256>>>(W_out, VV, Bhi, Blo);
    {
        dim3 g(NPAD/128, MM/128);
        hmma_gemm<<<g, 256>>>(Ahi, Alo, Bhi, Blo, b_out, out, VV, VV);
    }

    // h_final = [h0(S-1), h1(S-1)]
    if (outh) final_kernel<<<BH/256, 256>>>(outh);
}

// round 9
// speedup vs baseline: 2.0525x; 1.2072x over previous
#include <cuda_runtime.h>
#include <cuda_bf16.h>
#include <math.h>
#include <stdint.h>

// Problem dims (fixed by the dataset)
#define SS 128      // sequence length
#define BB 64       // batch
#define HH 1024     // hidden = embedding dim
#define VV 10000    // vocab
#define MM (SS*BB)  // 8192 rows for the batched GEMMs
#define BH (BB*HH)  // 65536
#define NPAD 10240  // vocab padded to 128-multiple for tensor tiles
#define GRIDB 64    // scan grid (64 j-tiles of 16)

// ---------------- device scratch (no allocations allowed) ----------------
// Hidden slabs: split-bf16, A-operand layout [m = t*64 + b][k], rows 0..63 = h(0).
__device__ __align__(16) float g_pre0[MM * HH];          // drive layer 0, [t][b][j]
__device__ __align__(16) float g_pre1[MM * HH];          // drive layer 1, [t][b][j]
__device__ __align__(16) __nv_bfloat16 g_S0hi[(SS+1) * BH];
__device__ __align__(16) __nv_bfloat16 g_S0lo[(SS+1) * BH];
__device__ __align__(16) __nv_bfloat16 g_S1hi[(SS+1) * BH];
__device__ __align__(16) __nv_bfloat16 g_S1lo[(SS+1) * BH];
__device__ __align__(16) __nv_bfloat16 g_Ahi[MM * HH];   // gathered emb (hi)
__device__ __align__(16) __nv_bfloat16 g_Alo[MM * HH];   // gathered emb (lo)
__device__ __align__(16) __nv_bfloat16 g_Bhi[NPAD * HH]; // weight operand (hi)
__device__ __align__(16) __nv_bfloat16 g_Blo[NPAD * HH]; // weight operand (lo)
__device__ __align__(16) float g_bias1c[HH];             // b_ih1 + b_hh1
__device__ unsigned g_arrive;                            // grid barrier: arrivals
__device__ unsigned g_release;                           // grid barrier: generation

// ---------------- generic helpers ----------------
__device__ __forceinline__ unsigned ldcg_u(const unsigned* p) {
    unsigned v; asm volatile("ld.global.cg.u32 %0, [%1];" : "=r"(v) : "l"(p)); return v;
}
__device__ __forceinline__ unsigned smem_u32(const void* p) {
    unsigned a;
    asm("{ .reg .u64 t; cvta.to.shared.u64 t, %1; cvt.u32.u64 %0, t; }" : "=r"(a) : "l"(p));
    return a;
}
__device__ __forceinline__ void cp_async16(unsigned dst, const void* src) {
    asm volatile("cp.async.cg.shared.global [%0], [%1], 16;" :: "r"(dst), "l"(src));
}
__device__ __forceinline__ void cp_commit() {
    asm volatile("cp.async.commit_group;");
}
template<int N>
__device__ __forceinline__ void cp_wait() {
    asm volatile("cp.async.wait_group %0;" :: "n"(N));
}

// grid barrier over NB resident blocks
__device__ __forceinline__ void grid_barrier(unsigned want, unsigned NB) {
    __syncthreads();
    if (threadIdx.x == 0) {
        __threadfence();
        unsigned prev = atomicAdd(&g_arrive, 1u);
        if (prev == want * NB - 1u) {
            atomicExch(&g_release, want);
        }
        while (ldcg_u(&g_release) < want) { __nanosleep(32); }
    }
    __syncthreads();
}

// ---------------- split-bf16 helpers ----------------
__device__ __forceinline__ void split4_store(float4 v,
    __nv_bfloat16* hi, __nv_bfloat16* lo, size_t off)
{
    float vv[4] = {v.x, v.y, v.z, v.w};
    uint32_t ph[2], pl[2];
    #pragma unroll
    for (int e = 0; e < 2; e++) {
        __nv_bfloat16 h0 = __float2bfloat16(vv[e*2+0]);
        __nv_bfloat16 h1 = __float2bfloat16(vv[e*2+1]);
        __nv_bfloat16 l0 = __float2bfloat16(vv[e*2+0] - __bfloat162float(h0));
        __nv_bfloat16 l1 = __float2bfloat16(vv[e*2+1] - __bfloat162float(h1));
        __nv_bfloat162 hh; hh.x = h0; hh.y = h1; ph[e] = *(uint32_t*)&hh;
        __nv_bfloat162 ll; ll.x = l0; ll.y = l1; pl[e] = *(uint32_t*)&ll;
    }
    *(uint2*)(hi + off) = make_uint2(ph[0], ph[1]);
    *(uint2*)(lo + off) = make_uint2(pl[0], pl[1]);
}

// weights [Nrows][K] -> hi/lo, zero-padded rows up to grid coverage
__global__ void __launch_bounds__(256) conv_w(
    const float* __restrict__ W, int Nrows,
    __nv_bfloat16* __restrict__ hi, __nv_bfloat16* __restrict__ lo)
{
    const int idx = blockIdx.x * 256 + threadIdx.x;
    const int row = idx >> 8;
    const int c4  = (idx & 255) * 4;
    float4 v = make_float4(0.f, 0.f, 0.f, 0.f);
    if (row < Nrows) v = *(const float4*)&W[(size_t)row * HH + c4];
    split4_store(v, hi, lo, (size_t)row * HH + c4);
}

// gathered, scaled embedding -> hi/lo A slab [m][K]
__global__ void __launch_bounds__(256) conv_gather(
    const int* __restrict__ gidx, const float* __restrict__ emb,
    __nv_bfloat16* __restrict__ hi, __nv_bfloat16* __restrict__ lo)
{
    const int idx = blockIdx.x * 256 + threadIdx.x;
    const int m  = idx >> 8;
    const int c4 = (idx & 255) * 4;
    float4 v = *(const float4*)&emb[(size_t)gidx[m] * HH + c4];
    v.x *= 32.f; v.y *= 32.f; v.z *= 32.f; v.w *= 32.f;
    split4_store(v, hi, lo, (size_t)m * HH + c4);
}

// initial hidden [l][b][k] fp32 -> slab rows 0..63 (hi/lo), both layers
__global__ void __launch_bounds__(256) init_hid(const float* __restrict__ hidden)
{
    const int i = blockIdx.x * 256 + threadIdx.x;   // grid covers 2*BH/4
    const int l = i >= (BH / 4);
    const int r = i - l * (BH / 4);
    const int b = r >> 8, c4 = (r & 255) * 4;
    float4 v = *(const float4*)&hidden[(size_t)l * BH + (size_t)b * HH + c4];
    if (l == 0) split4_store(v, g_S0hi, g_S0lo, (size_t)b * HH + c4);
    else        split4_store(v, g_S1hi, g_S1lo, (size_t)b * HH + c4);
}

// ---------------- mma.sync bf16 split GEMM: C = A@B^T + bias (R8, unchanged) --
#define BKC   32
#define TSTR  40
#define NCHK  96

__device__ __forceinline__ void ldm_x4(uint32_t* r, uint32_t addr) {
    asm volatile("ldmatrix.sync.aligned.m8n8.x4.shared.b16 {%0,%1,%2,%3}, [%4];"
                 : "=r"(r[0]), "=r"(r[1]), "=r"(r[2]), "=r"(r[3]) : "r"(addr));
}
__device__ __forceinline__ void mma16816(float* c, const uint32_t* a, const uint32_t* b) {
    asm volatile(
        "mma.sync.aligned.m16n8k16.row.col.f32.bf16.bf16.f32 "
        "{%0,%1,%2,%3}, {%4,%5,%6,%7}, {%8,%9}, {%0,%1,%2,%3};"
        : "+f"(c[0]), "+f"(c[1]), "+f"(c[2]), "+f"(c[3])
        : "r"(a[0]), "r"(a[1]), "r"(a[2]), "r"(a[3]), "r"(b[0]), "r"(b[1]));
}

__global__ void __launch_bounds__(256, 1) hmma_gemm(
    const __nv_bfloat16* __restrict__ Ahi, const __nv_bfloat16* __restrict__ Alo,
    const __nv_bfloat16* __restrict__ Bhi, const __nv_bfloat16* __restrict__ Blo,
    const float* __restrict__ bias, float* __restrict__ C, int ldc, int Nvalid)
{
    __shared__ __nv_bfloat16 As[2][128 * TSTR];
    __shared__ __nv_bfloat16 Bs[2][128 * TSTR];

    const int tid  = threadIdx.x;
    const int wrp  = tid >> 5;
    const int lane = tid & 31;
    const int wm   = (wrp >> 2) * 64;
    const int wn   = (wrp & 3) * 32;
    const int bm   = blockIdx.y * 128;
    const int bn   = blockIdx.x * 128;

    const uint32_t as_base = smem_u32(&As[0][0]);
    const uint32_t bs_base = smem_u32(&Bs[0][0]);
    const uint32_t bufstride = 128u * TSTR * 2u;

    const uint32_t a_row = (uint32_t)(wm + (lane & 15));
    const uint32_t a_col = (uint32_t)((lane >> 4) * 8);
    const uint32_t b_row = (uint32_t)(wn + ((lane >> 4) * 8) + (lane & 7));
    const uint32_t b_col = (uint32_t)(((lane >> 3) & 1) * 8);

    float acc[4][4][4] = {};

    const int g_row = tid >> 1;
    const int g_c   = (tid & 1) * 2;

    {
        const __nv_bfloat16* Ap = Ahi + (size_t)(bm + g_row) * HH;
        const __nv_bfloat16* Bp = Bhi + (size_t)(bn + g_row) * HH;
        const uint32_t da = as_base + (uint32_t)(g_row * TSTR * 2) + (uint32_t)g_c * 16u;
        const uint32_t db = bs_base + (uint32_t)(g_row * TSTR * 2) + (uint32_t)g_c * 16u;
        cp_async16(da,       Ap + g_c * 8);
        cp_async16(da + 16u, Ap + g_c * 8 + 8);
        cp_async16(db,       Bp + g_c * 8);
        cp_async16(db + 16u, Bp + g_c * 8 + 8);
        cp_commit();
    }

    for (int c = 0; c < NCHK; c++) {
        if (c + 1 < NCHK) {
            const int nc  = c + 1;
            const int seg = nc >> 5;
            const int kk  = (nc & 31) * BKC;
            const __nv_bfloat16* Asrc = (seg == 2) ? Alo : Ahi;
            const __nv_bfloat16* Bsrc = (seg == 1) ? Blo : Bhi;
            const uint32_t boff = (uint32_t)(nc & 1) * bufstride;
            const __nv_bfloat16* Ap = Asrc + (size_t)(bm + g_row) * HH + kk;
            const __nv_bfloat16* Bp = Bsrc + (size_t)(bn + g_row) * HH + kk;
            const uint32_t da = as_base + boff + (uint32_t)(g_row * TSTR * 2) + (uint32_t)g_c * 16u;
            const uint32_t db = bs_base + boff + (uint32_t)(g_row * TSTR * 2) + (uint32_t)g_c * 16u;
            cp_async16(da,       Ap + g_c * 8);
            cp_async16(da + 16u, Ap + g_c * 8 + 8);
            cp_async16(db,       Bp + g_c * 8);
            cp_async16(db + 16u, Bp + g_c * 8 + 8);
            cp_commit();
            cp_wait<1>();
        } else {
            cp_wait<0>();
        }
        __syncthreads();

        const uint32_t boff = (uint32_t)(c & 1) * bufstride;
        #pragma unroll
        for (int ks = 0; ks < 2; ks++) {
            uint32_t a[4][4], b[2][4];
            #pragma unroll
            for (int mt = 0; mt < 4; mt++) {
                const uint32_t addr = as_base + boff +
                    ((a_row + mt * 16u) * TSTR + a_col + (uint32_t)ks * 16u) * 2u;
                ldm_x4(a[mt], addr);
            }
            #pragma unroll
            for (int np = 0; np < 2; np++) {
                const uint32_t addr = bs_base + boff +
                    ((b_row + np * 16u) * TSTR + b_col + (uint32_t)ks * 16u) * 2u;
                ldm_x4(b[np], addr);
            }
            #pragma unroll
            for (int mt = 0; mt < 4; mt++) {
                #pragma unroll
                for (int nt = 0; nt < 4; nt++) {
                    uint32_t bb[2] = { b[nt >> 1][(nt & 1) * 2],
                                       b[nt >> 1][(nt & 1) * 2 + 1] };
                    mma16816(acc[mt][nt], a[mt], bb);
                }
            }
        }
        __syncthreads();
    }

    const int er = lane >> 2;
    const int ec = (lane & 3) * 2;
    #pragma unroll
    for (int mt = 0; mt < 4; mt++) {
        const int m0 = bm + wm + mt * 16 + er;
        #pragma unroll
        for (int nt = 0; nt < 4; nt++) {
            const int n0 = bn + wn + nt * 8 + ec;
            if (n0 + 1 < Nvalid) {
                const float bz0 = __ldg(&bias[n0]);
                const float bz1 = __ldg(&bias[n0 + 1]);
                *(float2*)&C[(size_t)m0 * ldc + n0] =
                    make_float2(acc[mt][nt][0] + bz0, acc[mt][nt][1] + bz1);
                *(float2*)&C[(size_t)(m0 + 8) * ldc + n0] =
                    make_float2(acc[mt][nt][2] + bz0, acc[mt][nt][3] + bz1);
            } else if (n0 < Nvalid) {
                const float bz0 = __ldg(&bias[n0]);
                C[(size_t)m0 * ldc + n0]       = acc[mt][nt][0] + bz0;
                C[(size_t)(m0 + 8) * ldc + n0] = acc[mt][nt][2] + bz0;
            }
        }
    }
}

// ---------------- tensor-core recurrence scan --------------------------------
// h(t+1)[b][j] = tanh( pre[t][b][j] + sum_k W[j][k] h(t)[b][k] + bias[j] )
// D = A@B^T with A = W rows (m=j), B = slab rows t*64+b (n=b).
// 64 blocks x 128 threads; block owns 16 j (W tile hi/lo SMEM-resident).
// B (h) streamed in 4 double-buffered k-chunks of 256. 3-term split MMA.
// Output stored as split-bf16 slab rows (t+1)*64+b -> feeds next step + GEMMs.
#define JT   16
#define WS   1032    // bf16 stride for W rows  (2064 B; %128 == 16 -> ldmatrix-clean)
#define BS   264     // bf16 stride for B rows  (528 B;  %128 == 16 -> ldmatrix-clean)
#define SCK  256     // k-chunk
#define SCAN_SMEM (size_t)((2*JT*WS + 4*64*BS) * 2 + 64*17*4)

__global__ void __launch_bounds__(128, 1) rec_scan_mma(
    const float* __restrict__ pre,     // [SS][B][H]
    const float* __restrict__ W,       // [H][H] fp32 (row = out j)
    const float* __restrict__ bias,    // [H] or nullptr
    __nv_bfloat16* __restrict__ Shi,   // slab hi [(SS+1)*64][H]
    __nv_bfloat16* __restrict__ Slo,   // slab lo
    unsigned bar0)
{
    extern __shared__ __nv_bfloat16 smb[];
    __nv_bfloat16* Wh = smb;                   // [JT][WS]
    __nv_bfloat16* Wl = Wh + JT * WS;
    __nv_bfloat16* Bh = Wl + JT * WS;          // [2][64][BS]
    __nv_bfloat16* Bl = Bh + 2 * 64 * BS;
    float* Ds = (float*)(Bl + 2 * 64 * BS);    // [64][17]

    const int tid  = threadIdx.x;
    const int wrp  = tid >> 5;
    const int lane = tid & 31;
    const int j0g  = blockIdx.x * JT;

    // ---- one-time: W tile fp32 -> split bf16 in SMEM
    for (int idx = tid; idx < JT * 1024; idx += 128) {
        const int row = idx >> 10, col = idx & 1023;
        const float v = W[(size_t)(j0g + row) * HH + col];
        const __nv_bfloat16 h = __float2bfloat16(v);
        Wh[row * WS + col] = h;
        Wl[row * WS + col] = __float2bfloat16(v - __bfloat162float(h));
    }
    // per-thread epilogue constants: thread handles (b = tid&63, 8 j's)
    const int eb = tid & 63, ehalf = tid >> 6;
    float breg[8];
    #pragma unroll
    for (int i = 0; i < 8; i++)
        breg[i] = bias ? bias[j0g + ehalf * 8 + i] : 0.0f;
    __syncthreads();

    const uint32_t wh_b = smem_u32(Wh), wl_b = smem_u32(Wl);
    const uint32_t bh_b = smem_u32(Bh), bl_b = smem_u32(Bl);

    // ldmatrix lane addressing
    const uint32_t a_row = (uint32_t)(lane & 15);
    const uint32_t a_sel = (uint32_t)((lane >> 4) * 8);
    const uint32_t b_row = (uint32_t)(wrp * 16 + ((lane >> 4) * 8) + (lane & 7));
    const uint32_t b_sel = (uint32_t)(((lane >> 3) & 1) * 8);

    const int er = lane >> 2, ec = (lane & 3) * 2;

    for (int t = 0; t < SS; t++) {
        const __nv_bfloat16* srcH = Shi + (size_t)t * BH;
        const __nv_bfloat16* srcL = Slo + (size_t)t * BH;

        // stage chunk 0: 64 rows x 256 bf16 per operand (2048 cp16 x2)
        #pragma unroll
        for (int r = 0; r < 16; r++) {
            const int idx = tid + r * 128;     // 0..2047
            const int row = idx >> 5, cc = idx & 31;
            const uint32_t d = (uint32_t)(row * BS * 2 + cc * 16);
            const size_t  s = (size_t)row * HH + cc * 8;
            cp_async16(bh_b + d, srcH + s);
            cp_async16(bl_b + d, srcL + s);
        }
        cp_commit();

        float acc[2][4] = {};

        #pragma unroll
        for (int c = 0; c < 4; c++) {
            if (c < 3) {
                const uint32_t bo = (uint32_t)((c + 1) & 1) * 64u * BS * 2u;
                const int k0 = (c + 1) * SCK;
                #pragma unroll
                for (int r = 0; r < 16; r++) {
                    const int idx = tid + r * 128;
                    const int row = idx >> 5, cc = idx & 31;
                    const uint32_t d = bo + (uint32_t)(row * BS * 2 + cc * 16);
                    const size_t  s = (size_t)row * HH + k0 + cc * 8;
                    cp_async16(bh_b + d, srcH + s);
                    cp_async16(bl_b + d, srcL + s);
                }
                cp_commit();
                cp_wait<1>();
            } else {
                cp_wait<0>();
            }
            __syncthreads();

            const uint32_t bo = (uint32_t)(c & 1) * 64u * BS * 2u;
            #pragma unroll
            for (int ks = 0; ks < 16; ks++) {
                uint32_t ah[4], al[4], bhf[4], blf[4];
                const uint32_t acol = (uint32_t)(c * SCK + ks * 16) + a_sel;
                ldm_x4(ah, wh_b + (a_row * WS + acol) * 2u);
                ldm_x4(al, wl_b + (a_row * WS + acol) * 2u);
                const uint32_t boff2 = bo + (b_row * BS + (uint32_t)(ks * 16) + b_sel) * 2u;
                ldm_x4(bhf, bh_b + boff2);
                ldm_x4(blf, bl_b + boff2);
                #pragma unroll
                for (int nt = 0; nt < 2; nt++) {
                    uint32_t bbh[2] = { bhf[nt * 2], bhf[nt * 2 + 1] };
                    uint32_t bbl[2] = { blf[nt * 2], blf[nt * 2 + 1] };
                    mma16816(acc[nt], ah, bbh);
                    mma16816(acc[nt], ah, bbl);
                    mma16816(acc[nt], al, bbh);
                }
            }
            __syncthreads();
        }

        // D[j][b] frags -> SMEM [b][j]
        #pragma unroll
        for (int nt = 0; nt < 2; nt++) {
            const int bc = wrp * 16 + nt * 8 + ec;
            Ds[bc * 17 + er]           = acc[nt][0];
            Ds[(bc + 1) * 17 + er]     = acc[nt][1];
            Ds[bc * 17 + er + 8]       = acc[nt][2];
            Ds[(bc + 1) * 17 + er + 8] = acc[nt][3];
        }
        __syncthreads();

        // epilogue: +pre +bias, tanh, re-split, store slab row (t+1)*64+b
        {
            const float* pp = pre + (size_t)t * BH + (size_t)eb * HH + j0g + ehalf * 8;
            const float4 p0 = __ldg((const float4*)pp);
            const float4 p1 = __ldg((const float4*)(pp + 4));
            const float pv[8] = {p0.x, p0.y, p0.z, p0.w, p1.x, p1.y, p1.z, p1.w};
            __nv_bfloat16 oh[8], ol[8];
            #pragma unroll
            for (int i = 0; i < 8; i++) {
                const float v = Ds[eb * 17 + ehalf * 8 + i] + pv[i] + breg[i];
                const float th = tanhf(v);
                oh[i] = __float2bfloat16(th);
                ol[i] = __float2bfloat16(th - __bfloat162float(oh[i]));
            }
            const size_t o = (size_t)((t + 1) * 64 + eb) * HH + j0g + ehalf * 8;
            *(uint4*)(Shi + o) = *(const uint4*)oh;
            *(uint4*)(Slo + o) = *(const uint4*)ol;
        }

        grid_barrier(bar0 + (unsigned)t + 1u, GRIDB);
    }
}

// ---------------- tiny utility kernels ----------------
__global__ void init_kernel(const float* __restrict__ b_ih1,
                            const float* __restrict__ b_hh1)
{
    const int i = blockIdx.x * 256 + threadIdx.x;   // grid covers HH
    g_bias1c[i] = b_ih1[i] + b_hh1[i];
    if (i == 0) { g_arrive = 0u; g_release = 0u; }
}

__global__ void __launch_bounds__(256) final_kernel(float* __restrict__ outh)
{
    const int i = blockIdx.x * 256 + threadIdx.x;   // grid covers BH
    const size_t o = (size_t)(SS * 64) * HH + i;    // rows 8192..8255 cover [b][j]
    outh[i]      = __bfloat162float(g_S0hi[o]) + __bfloat162float(g_S0lo[o]);
    outh[BH + i] = __bfloat162float(g_S1hi[o]) + __bfloat162float(g_S1lo[o]);
}

// ---------------- launcher ----------------
extern "C" void kernel_launch(void* const* d_in, const int* in_sizes, int n_in,
                              void* d_out, int out_size)
{
    const int*   inputs = (const int*)  d_in[0];  // [S,B]
    const float* hidden = (const float*)d_in[1];  // [L,B,H]
    const float* emb    = (const float*)d_in[2];  // [V,E]
    const float* W_ih   = (const float*)d_in[3];  // [L,H,E]
    const float* b_ih   = (const float*)d_in[4];  // [L,H]
    const float* W_hh   = (const float*)d_in[5];  // [L,H,H]
    const float* b_hh   = (const float*)d_in[6];  // [L,H]
    const float* W_out  = (const float*)d_in[7];  // [V,H]
    const float* b_out  = (const float*)d_in[8];  // [V]

    const float* W_ih0 = W_ih;
    const float* W_ih1 = W_ih + (size_t)HH * HH;
    const float* W_hh0 = W_hh;
    const float* W_hh1 = W_hh + (size_t)HH * HH;
    const float* b_ih0 = b_ih;
    const float* b_ih1 = b_ih + HH;
    const float* b_hh0 = b_hh;
    const float* b_hh1 = b_hh + HH;

    float *pre0, *pre1, *bias1c;
    __nv_bfloat16 *S0hi, *S0lo, *S1hi, *S1lo, *Ahi, *Alo, *Bhi, *Blo;
    cudaGetSymbolAddress((void**)&pre0,   g_pre0);
    cudaGetSymbolAddress((void**)&pre1,   g_pre1);
    cudaGetSymbolAddress((void**)&bias1c, g_bias1c);
    cudaGetSymbolAddress((void**)&S0hi,   g_S0hi);
    cudaGetSymbolAddress((void**)&S0lo,   g_S0lo);
    cudaGetSymbolAddress((void**)&S1hi,   g_S1hi);
    cudaGetSymbolAddress((void**)&S1lo,   g_S1lo);
    cudaGetSymbolAddress((void**)&Ahi,    g_Ahi);
    cudaGetSymbolAddress((void**)&Alo,    g_Alo);
    cudaGetSymbolAddress((void**)&Bhi,    g_Bhi);
    cudaGetSymbolAddress((void**)&Blo,    g_Blo);

    float* out = (float*)d_out;
    const long long logitsN = (long long)MM * VV;
    float* outh = ((long long)out_size >= logitsN + 2LL * BH) ? out + logitsN : nullptr;

    cudaFuncSetAttribute(rec_scan_mma, cudaFuncAttributeMaxDynamicSharedMemorySize,
                         (int)SCAN_SMEM);

    // bias1c + barrier reset (every replay)
    init_kernel<<<HH/256, 256>>>(b_ih1, b_hh1);
    // initial hidden -> slab rows 0..63 (both layers, split bf16)
    init_hid<<<(2*BH/4)/256, 256>>>(hidden);

    // Phase A: pre0 = (emb[tok]*32) @ W_ih0^T + b_ih0
    conv_gather<<<MM, 256>>>(inputs, emb, Ahi, Alo);
    conv_w<<<HH, 256>>>(W_ih0, HH, Bhi, Blo);
    {
        dim3 g(HH/128, MM/128);
        hmma_gemm<<<g, 256>>>(Ahi, Alo, Bhi, Blo, b_ih0, pre0, HH, HH);
    }

    // layer-0 scan (tensor cores)
    rec_scan_mma<<<GRIDB, 128, SCAN_SMEM>>>(pre0, W_hh0, b_hh0, S0hi, S0lo, 0u);

    // pre1 = H0all @ W_ih1^T + (b_ih1 + b_hh1) — consumes slab hi/lo directly
    conv_w<<<HH, 256>>>(W_ih1, HH, Bhi, Blo);
    {
        dim3 g(HH/128, MM/128);
        hmma_gemm<<<g, 256>>>(S0hi + (size_t)64*HH, S0lo + (size_t)64*HH,
                              Bhi, Blo, bias1c, pre1, HH, HH);
    }

    // layer-1 scan (continues the monotonic barrier counter at SS)
    rec_scan_mma<<<GRIDB, 128, SCAN_SMEM>>>(pre1, W_hh1, nullptr, S1hi, S1lo, (unsigned)SS);

    // logits = H1all @ W_out^T + b_out
    conv_w<<<NPAD, 256>>>(W_out, VV, Bhi, Blo);
    {
        dim3 g(NPAD/128, MM/128);
        hmma_gemm<<<g, 256>>>(S1hi + (size_t)64*HH, S1lo + (size_t)64*HH,
                              Bhi, Blo, b_out, out, VV, VV);
    }

    // h_final = [h0(S-1), h1(S-1)]
    if (outh) final_kernel<<<BH/256, 256>>>(outh);
}